// round 4
// baseline (speedup 1.0000x reference)
#include <cuda_runtime.h>
#include <cuda_bf16.h>
#include <cstdint>

#define NN 100000
#define EE 1600000

// ---------------- scratch (device globals) -----------------------------------
__device__ int   g_deg[NN];
__device__ int   g_off[NN];
__device__ int   g_cur[NN];
__device__ float g_dinv[NN];
__device__ int   g_srcs[EE];
__device__ int   g_bsum[128];
__device__ int   g_flag;
__device__ float g_uv[(size_t)NN * 256];
__device__ float g_h1[(size_t)NN * 128];
__device__ float g_h [(size_t)NN * 128];
// pre-split, pre-swizzled weight images: Wt[n][k] bf16, row stride 256B, XOR swizzle
__device__ __align__(16) unsigned char g_w1hi[256 * 256];
__device__ __align__(16) unsigned char g_w1lo[256 * 256];
__device__ __align__(16) unsigned char g_w2hi[256 * 256];
__device__ __align__(16) unsigned char g_w2lo[256 * 256];
__device__ __align__(16) unsigned char g_wfhi[64 * 256];
__device__ __align__(16) unsigned char g_wflo[64 * 256];

// ---------------- helpers -----------------------------------------------------
__device__ __forceinline__ uint32_t smem_u32(const void* p) {
    uint32_t a;
    asm("{ .reg .u64 t; cvta.to.shared.u64 t, %1; cvt.u32.u64 %0, t; }" : "=r"(a) : "l"(p));
    return a;
}
__device__ __forceinline__ uint32_t swz(int row, int col) {
    uint32_t off = (uint32_t)row * 256u + (uint32_t)col * 2u;
    return off ^ (((uint32_t)row & 7u) << 4);
}
__device__ __forceinline__ void ldsm_x4(uint32_t* r, uint32_t addr) {
    asm volatile("ldmatrix.sync.aligned.m8n8.x4.shared.b16 {%0,%1,%2,%3}, [%4];"
                 : "=r"(r[0]), "=r"(r[1]), "=r"(r[2]), "=r"(r[3]) : "r"(addr));
}
__device__ __forceinline__ void mma_bf16(float* c, const uint32_t* a, const uint32_t* b) {
    asm volatile("mma.sync.aligned.m16n8k16.row.col.f32.bf16.bf16.f32 "
                 "{%0,%1,%2,%3}, {%4,%5,%6,%7}, {%8,%9}, {%0,%1,%2,%3};"
                 : "+f"(c[0]), "+f"(c[1]), "+f"(c[2]), "+f"(c[3])
                 : "r"(a[0]), "r"(a[1]), "r"(a[2]), "r"(a[3]), "r"(b[0]), "r"(b[1]));
}

// ---------------- CSR build ---------------------------------------------------
__global__ void k_zero() {
    int i = blockIdx.x * blockDim.x + threadIdx.x;
    if (i < NN) g_deg[i] = 0;
    if (i == 0) g_flag = 0;
}
__global__ void k_detect(const unsigned int* __restrict__ w) {
    int i = blockIdx.x * blockDim.x + threadIdx.x;
    if (w[2 * i + 1] != 0u) g_flag = 1;
}
__device__ __forceinline__ int ld_edge(const void* ei, long long pos, int is64) {
    if (is64) return (int)((const long long*)ei)[pos];
    return ((const int*)ei)[pos];
}
__global__ void k_hist(const void* __restrict__ ei) {
    int e = blockIdx.x * blockDim.x + threadIdx.x;
    if (e >= EE) return;
    int is64 = (g_flag == 0);
    atomicAdd(&g_deg[ld_edge(ei, (long long)EE + e, is64)], 1);
}
__global__ void k_scan1() {
    __shared__ int sh[1024];
    int i = blockIdx.x * 1024 + threadIdx.x;
    int v = (i < NN) ? g_deg[i] : 0;
    sh[threadIdx.x] = v;
    __syncthreads();
    for (int d = 1; d < 1024; d <<= 1) {
        int t = (threadIdx.x >= d) ? sh[threadIdx.x - d] : 0;
        __syncthreads();
        sh[threadIdx.x] += t;
        __syncthreads();
    }
    if (i < NN) g_off[i] = sh[threadIdx.x] - v;
    if (threadIdx.x == 1023) g_bsum[blockIdx.x] = sh[1023];
}
__global__ void k_scan2() {
    __shared__ int sh[128];
    int i = threadIdx.x;
    const int NB = (NN + 1023) / 1024;
    int v = (i < NB) ? g_bsum[i] : 0;
    sh[i] = v;
    __syncthreads();
    for (int d = 1; d < 128; d <<= 1) {
        int t = (i >= d) ? sh[i - d] : 0;
        __syncthreads();
        sh[i] += t;
        __syncthreads();
    }
    if (i < NB) g_bsum[i] = sh[i] - v;
}
__global__ void k_scan3() {
    int i = blockIdx.x * 1024 + threadIdx.x;
    if (i >= NN) return;
    int o = g_off[i] + g_bsum[i >> 10];
    g_off[i] = o;
    g_cur[i] = o;
    int d = g_deg[i];
    g_dinv[i] = 1.0f / (float)(d > 1 ? d : 1);
}
__global__ void k_scatter(const void* __restrict__ ei) {
    int e = blockIdx.x * blockDim.x + threadIdx.x;
    if (e >= EE) return;
    int is64 = (g_flag == 0);
    int s = ld_edge(ei, (long long)e, is64);
    int d = ld_edge(ei, (long long)EE + e, is64);
    g_srcs[atomicAdd(&g_cur[d], 1)] = s;
}

// ---------------- weight prep -------------------------------------------------
__global__ void k_prep_w(const float* __restrict__ W1l, const float* __restrict__ W1r,
                         const float* __restrict__ W2l, const float* __restrict__ W2r,
                         const float* __restrict__ Wlin) {
    int i = blockIdx.x * blockDim.x + threadIdx.x;
    float v;
    unsigned char *hi, *lo;
    uint32_t off;
    if (i < 65536) {
        int layer = i >> 15, e = i & 32767;
        int n = e >> 7, k = e & 127;
        const float* Wl = layer ? W2l : W1l;
        const float* Wr = layer ? W2r : W1r;
        v = (n < 128) ? Wl[k * 128 + n] : Wr[k * 128 + (n - 128)];
        hi = layer ? g_w2hi : g_w1hi;
        lo = layer ? g_w2lo : g_w1lo;
        off = swz(n, k);
    } else if (i < 65536 + 8192) {
        int e = i - 65536;
        int n = e >> 7, k = e & 127;
        v = Wlin[k * 64 + n];
        hi = g_wfhi; lo = g_wflo;
        off = swz(n, k);
    } else return;
    __nv_bfloat16 h = __float2bfloat16_rn(v);
    __nv_bfloat16 l = __float2bfloat16_rn(v - __bfloat162float(h));
    *(__nv_bfloat16*)(hi + off) = h;
    *(__nv_bfloat16*)(lo + off) = l;
}

// ---------------- mma.sync GEMM ----------------------------------------------
template <int NC>
__global__ void __launch_bounds__(256, 1) k_gemm_mma(
    const float* __restrict__ A,
    const unsigned char* __restrict__ Bhi, const unsigned char* __restrict__ Blo,
    const float* __restrict__ bias,
    float* __restrict__ C) {
    extern __shared__ unsigned char sm[];
    const int BIAS = 0;
    const int AHI = 1024;
    const int ALO = AHI + 32768;
    const int BHI = ALO + 32768;
    const int BLO = BHI + NC * 256;
    uint32_t sb = smem_u32(sm);
    int tid = threadIdx.x, wid = tid >> 5, lane = tid & 31;

    const int BW = NC * 256 / 16;
    for (int i = tid; i < BW; i += 256) {
        ((float4*)(sm + BHI))[i] = ((const float4*)Bhi)[i];
        ((float4*)(sm + BLO))[i] = ((const float4*)Blo)[i];
    }
    if (bias) for (int i = tid; i < NC; i += 256) ((float*)(sm + BIAS))[i] = bias[i];

    int row0 = blockIdx.x * 128;
    {
        int r = tid >> 1, half = tid & 1;
        int row = row0 + r;
        const float* ap = A + (size_t)row * 128 + half * 64;
        for (int cc = 0; cc < 64; cc += 4) {
            float4 v = (row < NN) ? *(const float4*)(ap + cc)
                                  : make_float4(0.f, 0.f, 0.f, 0.f);
            __nv_bfloat16 hx = __float2bfloat16_rn(v.x), hy = __float2bfloat16_rn(v.y);
            __nv_bfloat16 hz = __float2bfloat16_rn(v.z), hw = __float2bfloat16_rn(v.w);
            __nv_bfloat162 h0, h1, l0, l1;
            h0.x = hx; h0.y = hy; h1.x = hz; h1.y = hw;
            l0.x = __float2bfloat16_rn(v.x - __bfloat162float(hx));
            l0.y = __float2bfloat16_rn(v.y - __bfloat162float(hy));
            l1.x = __float2bfloat16_rn(v.z - __bfloat162float(hz));
            l1.y = __float2bfloat16_rn(v.w - __bfloat162float(hw));
            uint32_t so = swz(r, half * 64 + cc);
            *(__nv_bfloat162*)(sm + AHI + so)     = h0;
            *(__nv_bfloat162*)(sm + AHI + so + 4) = h1;
            *(__nv_bfloat162*)(sm + ALO + so)     = l0;
            *(__nv_bfloat162*)(sm + ALO + so + 4) = l1;
        }
    }
    __syncthreads();

    const int WARP_N = NC / 2;
    const int NPAIRS = WARP_N / 16;
    const int NB8    = WARP_N / 8;
    int warp_m = (wid & 3) * 32;
    int warp_n = (wid >> 2) * WARP_N;

    float c[2][NB8][4];
#pragma unroll
    for (int mb = 0; mb < 2; mb++)
#pragma unroll
        for (int nb = 0; nb < NB8; nb++)
#pragma unroll
            for (int j = 0; j < 4; j++) c[mb][nb][j] = 0.f;

    int a_r = ((lane >> 3) & 1) * 8 + (lane & 7);
    int a_c = (lane >> 4) * 8;
    int b_r = (lane >> 4) * 8 + (lane & 7);
    int b_c = ((lane >> 3) & 1) * 8;

#pragma unroll
    for (int pass = 0; pass < 3; pass++) {
        uint32_t abase = sb + (pass == 2 ? ALO : AHI);
        uint32_t bbase = sb + (pass == 1 ? BLO : BHI);
#pragma unroll
        for (int k = 0; k < 128; k += 16) {
            uint32_t afr[2][4];
#pragma unroll
            for (int mb = 0; mb < 2; mb++)
                ldsm_x4(afr[mb], abase + swz(warp_m + mb * 16 + a_r, k + a_c));
#pragma unroll
            for (int np = 0; np < NPAIRS; np++) {
                uint32_t bfr[4];
                ldsm_x4(bfr, bbase + swz(warp_n + np * 16 + b_r, k + b_c));
#pragma unroll
                for (int mb = 0; mb < 2; mb++) {
                    mma_bf16(c[mb][np * 2],     afr[mb], bfr);
                    mma_bf16(c[mb][np * 2 + 1], afr[mb], bfr + 2);
                }
            }
        }
    }

    int g = lane >> 2, tg = lane & 3;
    const float* bs = (const float*)(sm + BIAS);
#pragma unroll
    for (int mb = 0; mb < 2; mb++) {
#pragma unroll
        for (int nb = 0; nb < NB8; nb++) {
            int col = warp_n + nb * 8 + tg * 2;
            float bx = 0.f, by = 0.f;
            if (bias) { bx = bs[col]; by = bs[col + 1]; }
            int r1 = row0 + warp_m + mb * 16 + g;
            if (r1 < NN)
                *(float2*)(C + (size_t)r1 * NC + col) =
                    make_float2(c[mb][nb][0] + bx, c[mb][nb][1] + by);
            int r2 = r1 + 8;
            if (r2 < NN)
                *(float2*)(C + (size_t)r2 * NC + col) =
                    make_float2(c[mb][nb][2] + bx, c[mb][nb][3] + by);
        }
    }
}

// ---------------- aggregation: lane-parallel indices + pipelined gathers ------
__global__ void __launch_bounds__(256) k_agg(
    const float* __restrict__ uv,
    const float* __restrict__ bias,
    const float* __restrict__ res,
    float* __restrict__ out) {
    int node = blockIdx.x * 8 + (threadIdx.x >> 5);
    if (node >= NN) return;
    int lane = threadIdx.x & 31;
    int off = g_off[node];
    int d = g_deg[node];

    float ax = 0.f, ay = 0.f, az = 0.f, aw = 0.f;
    const float* uvb = uv + (size_t)lane * 4;

    for (int base = 0; base < d; base += 32) {
        int n = d - base;
        if (n > 32) n = 32;
        // coalesced: each lane loads one edge index
        int s = 0;
        if (lane < n) s = __ldg(&g_srcs[off + base + lane]);
        unsigned mask = 0xFFFFFFFFu;
        int j = 0;
        // 4-deep pipelined gathers (addresses known upfront via shfl)
        for (; j + 4 <= n; j += 4) {
            int s0 = __shfl_sync(mask, s, j);
            int s1 = __shfl_sync(mask, s, j + 1);
            int s2 = __shfl_sync(mask, s, j + 2);
            int s3 = __shfl_sync(mask, s, j + 3);
            float4 t0 = *(const float4*)(uvb + (size_t)s0 * 256);
            float4 t1 = *(const float4*)(uvb + (size_t)s1 * 256);
            float4 t2 = *(const float4*)(uvb + (size_t)s2 * 256);
            float4 t3 = *(const float4*)(uvb + (size_t)s3 * 256);
            ax += t0.x + t1.x + t2.x + t3.x;
            ay += t0.y + t1.y + t2.y + t3.y;
            az += t0.z + t1.z + t2.z + t3.z;
            aw += t0.w + t1.w + t2.w + t3.w;
        }
        for (; j < n; j++) {
            int sj = __shfl_sync(mask, s, j);
            float4 t = *(const float4*)(uvb + (size_t)sj * 256);
            ax += t.x; ay += t.y; az += t.z; aw += t.w;
        }
    }

    float di = g_dinv[node];
    float4 v = *(const float4*)(uv + (size_t)node * 256 + 128 + lane * 4);
    float4 b = *(const float4*)(bias + lane * 4);
    float rx = fmaf(ax, di, v.x + b.x);
    float ry = fmaf(ay, di, v.y + b.y);
    float rz = fmaf(az, di, v.z + b.z);
    float rw = fmaf(aw, di, v.w + b.w);
    if (res) {
        float4 h = *(const float4*)(res + (size_t)node * 128 + lane * 4);
        rx += h.x; ry += h.y; rz += h.z; rw += h.w;
    }
    rx = fmaxf(rx, 0.f); ry = fmaxf(ry, 0.f);
    rz = fmaxf(rz, 0.f); rw = fmaxf(rw, 0.f);
    *(float4*)(out + (size_t)node * 128 + lane * 4) = make_float4(rx, ry, rz, rw);
}

// ---------------- launch ------------------------------------------------------
extern "C" void kernel_launch(void* const* d_in, const int* in_sizes, int n_in,
                              void* d_out, int out_size) {
    const float* x    = (const float*)d_in[0];
    const void*  ei   = d_in[1];
    const float* W1l  = (const float*)d_in[2];
    const float* b1   = (const float*)d_in[3];
    const float* W1r  = (const float*)d_in[4];
    const float* W2l  = (const float*)d_in[5];
    const float* b2   = (const float*)d_in[6];
    const float* W2r  = (const float*)d_in[7];
    const float* Wlin = (const float*)d_in[8];
    const float* blin = (const float*)d_in[9];
    float* out = (float*)d_out;

    const size_t SM_DUAL  = 1024 + 2 * 32768 + 2 * 256 * 256;
    const size_t SM_FINAL = 1024 + 2 * 32768 + 2 * 64 * 256;
    cudaFuncSetAttribute(k_gemm_mma<256>, cudaFuncAttributeMaxDynamicSharedMemorySize, (int)SM_DUAL);
    cudaFuncSetAttribute(k_gemm_mma<64>,  cudaFuncAttributeMaxDynamicSharedMemorySize, (int)SM_FINAL);

    void *p_uv, *p_h1, *p_h, *p_w1h, *p_w1l, *p_w2h, *p_w2l, *p_wfh, *p_wfl;
    cudaGetSymbolAddress(&p_uv, g_uv);
    cudaGetSymbolAddress(&p_h1, g_h1);
    cudaGetSymbolAddress(&p_h,  g_h);
    cudaGetSymbolAddress(&p_w1h, g_w1hi);
    cudaGetSymbolAddress(&p_w1l, g_w1lo);
    cudaGetSymbolAddress(&p_w2h, g_w2hi);
    cudaGetSymbolAddress(&p_w2l, g_w2lo);
    cudaGetSymbolAddress(&p_wfh, g_wfhi);
    cudaGetSymbolAddress(&p_wfl, g_wflo);
    float* uv = (float*)p_uv;
    float* h1 = (float*)p_h1;
    float* h  = (float*)p_h;

    const int NB_N   = (NN + 255) / 256;
    const int NB_E   = (EE + 255) / 256;
    const int NB_SC  = (NN + 1023) / 1024;
    const int NB_TC  = (NN + 127) / 128;
    const int NB_AGG = (NN + 7) / 8;

    k_zero<<<NB_N, 256>>>();
    k_detect<<<16, 256>>>((const unsigned int*)ei);
    k_prep_w<<<(73728 + 255) / 256, 256>>>(W1l, W1r, W2l, W2r, Wlin);
    k_hist<<<NB_E, 256>>>(ei);
    k_scan1<<<NB_SC, 1024>>>();
    k_scan2<<<1, 128>>>();
    k_scan3<<<NB_SC, 1024>>>();
    k_scatter<<<NB_E, 256>>>(ei);

    k_gemm_mma<256><<<NB_TC, 256, SM_DUAL>>>(x, (unsigned char*)p_w1h, (unsigned char*)p_w1l, nullptr, uv);
    k_agg<<<NB_AGG, 256>>>(uv, b1, nullptr, h1);
    k_gemm_mma<256><<<NB_TC, 256, SM_DUAL>>>(h1, (unsigned char*)p_w2h, (unsigned char*)p_w2l, nullptr, uv);
    k_agg<<<NB_AGG, 256>>>(uv, b2, h1, h);
    k_gemm_mma<64><<<NB_TC, 256, SM_FINAL>>>(h, (unsigned char*)p_wfh, (unsigned char*)p_wfl, blin, out);
}

// round 5
// speedup vs baseline: 1.1438x; 1.1438x over previous
#include <cuda_runtime.h>
#include <cuda_bf16.h>
#include <cuda_fp16.h>
#include <cstdint>

#define NN 100000
#define EE 1600000

// ---------------- scratch (device globals) -----------------------------------
__device__ int   g_deg[NN];
__device__ int   g_off[NN];
__device__ int   g_cur[NN];
__device__ float g_dinv[NN];
__device__ int   g_srcs[EE];
__device__ int   g_bsum[128];
__device__ int   g_flag;
__device__ __half g_ub[(size_t)NN * 128];   // u = A@Wl, fp16 (gather aggregand)
__device__ float  g_v [(size_t)NN * 128];   // v = A@Wr, fp32
__device__ float  g_h1[(size_t)NN * 128];
__device__ float  g_h [(size_t)NN * 128];
// pre-split, pre-swizzled weight images: Wt[n][k] bf16, row stride 256B, XOR swizzle
__device__ __align__(16) unsigned char g_w1hi[256 * 256];
__device__ __align__(16) unsigned char g_w1lo[256 * 256];
__device__ __align__(16) unsigned char g_w2hi[256 * 256];
__device__ __align__(16) unsigned char g_w2lo[256 * 256];
__device__ __align__(16) unsigned char g_wfhi[64 * 256];
__device__ __align__(16) unsigned char g_wflo[64 * 256];

// ---------------- helpers -----------------------------------------------------
__device__ __forceinline__ uint32_t smem_u32(const void* p) {
    uint32_t a;
    asm("{ .reg .u64 t; cvta.to.shared.u64 t, %1; cvt.u32.u64 %0, t; }" : "=r"(a) : "l"(p));
    return a;
}
__device__ __forceinline__ uint32_t swz(int row, int col) {
    uint32_t off = (uint32_t)row * 256u + (uint32_t)col * 2u;
    return off ^ (((uint32_t)row & 7u) << 4);
}
__device__ __forceinline__ void ldsm_x4(uint32_t* r, uint32_t addr) {
    asm volatile("ldmatrix.sync.aligned.m8n8.x4.shared.b16 {%0,%1,%2,%3}, [%4];"
                 : "=r"(r[0]), "=r"(r[1]), "=r"(r[2]), "=r"(r[3]) : "r"(addr));
}
__device__ __forceinline__ void mma_bf16(float* c, const uint32_t* a, const uint32_t* b) {
    asm volatile("mma.sync.aligned.m16n8k16.row.col.f32.bf16.bf16.f32 "
                 "{%0,%1,%2,%3}, {%4,%5,%6,%7}, {%8,%9}, {%0,%1,%2,%3};"
                 : "+f"(c[0]), "+f"(c[1]), "+f"(c[2]), "+f"(c[3])
                 : "r"(a[0]), "r"(a[1]), "r"(a[2]), "r"(a[3]), "r"(b[0]), "r"(b[1]));
}

// ---------------- CSR build ---------------------------------------------------
__global__ void k_zero() {
    int i = blockIdx.x * blockDim.x + threadIdx.x;
    if (i < NN) g_deg[i] = 0;
    if (i == 0) g_flag = 0;
}
__global__ void k_detect(const unsigned int* __restrict__ w) {
    int i = blockIdx.x * blockDim.x + threadIdx.x;
    if (w[2 * i + 1] != 0u) g_flag = 1;
}
__device__ __forceinline__ int ld_edge(const void* ei, long long pos, int is64) {
    if (is64) return (int)((const long long*)ei)[pos];
    return ((const int*)ei)[pos];
}
__global__ void k_hist(const void* __restrict__ ei) {
    int e = blockIdx.x * blockDim.x + threadIdx.x;
    if (e >= EE) return;
    int is64 = (g_flag == 0);
    atomicAdd(&g_deg[ld_edge(ei, (long long)EE + e, is64)], 1);
}
__global__ void k_scan1() {
    __shared__ int sh[1024];
    int i = blockIdx.x * 1024 + threadIdx.x;
    int v = (i < NN) ? g_deg[i] : 0;
    sh[threadIdx.x] = v;
    __syncthreads();
    for (int d = 1; d < 1024; d <<= 1) {
        int t = (threadIdx.x >= d) ? sh[threadIdx.x - d] : 0;
        __syncthreads();
        sh[threadIdx.x] += t;
        __syncthreads();
    }
    if (i < NN) g_off[i] = sh[threadIdx.x] - v;
    if (threadIdx.x == 1023) g_bsum[blockIdx.x] = sh[1023];
}
__global__ void k_scan2() {
    __shared__ int sh[128];
    int i = threadIdx.x;
    const int NB = (NN + 1023) / 1024;
    int v = (i < NB) ? g_bsum[i] : 0;
    sh[i] = v;
    __syncthreads();
    for (int d = 1; d < 128; d <<= 1) {
        int t = (i >= d) ? sh[i - d] : 0;
        __syncthreads();
        sh[i] += t;
        __syncthreads();
    }
    if (i < NB) g_bsum[i] = sh[i] - v;
}
__global__ void k_scan3() {
    int i = blockIdx.x * 1024 + threadIdx.x;
    if (i >= NN) return;
    int o = g_off[i] + g_bsum[i >> 10];
    g_off[i] = o;
    g_cur[i] = o;
    int d = g_deg[i];
    g_dinv[i] = 1.0f / (float)(d > 1 ? d : 1);
}
__global__ void k_scatter(const void* __restrict__ ei) {
    int e = blockIdx.x * blockDim.x + threadIdx.x;
    if (e >= EE) return;
    int is64 = (g_flag == 0);
    int s = ld_edge(ei, (long long)e, is64);
    int d = ld_edge(ei, (long long)EE + e, is64);
    g_srcs[atomicAdd(&g_cur[d], 1)] = s;
}

// ---------------- weight prep -------------------------------------------------
__global__ void k_prep_w(const float* __restrict__ W1l, const float* __restrict__ W1r,
                         const float* __restrict__ W2l, const float* __restrict__ W2r,
                         const float* __restrict__ Wlin) {
    int i = blockIdx.x * blockDim.x + threadIdx.x;
    float v;
    unsigned char *hi, *lo;
    uint32_t off;
    if (i < 65536) {
        int layer = i >> 15, e = i & 32767;
        int n = e >> 7, k = e & 127;
        const float* Wl = layer ? W2l : W1l;
        const float* Wr = layer ? W2r : W1r;
        v = (n < 128) ? Wl[k * 128 + n] : Wr[k * 128 + (n - 128)];
        hi = layer ? g_w2hi : g_w1hi;
        lo = layer ? g_w2lo : g_w1lo;
        off = swz(n, k);
    } else if (i < 65536 + 8192) {
        int e = i - 65536;
        int n = e >> 7, k = e & 127;
        v = Wlin[k * 64 + n];
        hi = g_wfhi; lo = g_wflo;
        off = swz(n, k);
    } else return;
    __nv_bfloat16 h = __float2bfloat16_rn(v);
    __nv_bfloat16 l = __float2bfloat16_rn(v - __bfloat162float(h));
    *(__nv_bfloat16*)(hi + off) = h;
    *(__nv_bfloat16*)(lo + off) = l;
}

// ---------------- mma.sync GEMM ----------------------------------------------
// SPLIT=true (dual layer): cols [0,128) -> UB as fp16, cols [128,256) -> V fp32.
// SPLIT=false (head):      cols -> C fp32 with bias.
template <int NC, bool SPLIT>
__global__ void __launch_bounds__(256, 1) k_gemm_mma(
    const float* __restrict__ A,
    const unsigned char* __restrict__ Bhi, const unsigned char* __restrict__ Blo,
    const float* __restrict__ bias,
    float* __restrict__ C, __half* __restrict__ UB, float* __restrict__ V) {
    extern __shared__ unsigned char sm[];
    const int BIAS = 0;
    const int AHI = 1024;
    const int ALO = AHI + 32768;
    const int BHI = ALO + 32768;
    const int BLO = BHI + NC * 256;
    uint32_t sb = smem_u32(sm);
    int tid = threadIdx.x, wid = tid >> 5, lane = tid & 31;

    const int BW = NC * 256 / 16;
    for (int i = tid; i < BW; i += 256) {
        ((float4*)(sm + BHI))[i] = ((const float4*)Bhi)[i];
        ((float4*)(sm + BLO))[i] = ((const float4*)Blo)[i];
    }
    if (bias) for (int i = tid; i < NC; i += 256) ((float*)(sm + BIAS))[i] = bias[i];

    int row0 = blockIdx.x * 128;
    {
        int r = tid >> 1, half = tid & 1;
        int row = row0 + r;
        const float* ap = A + (size_t)row * 128 + half * 64;
        for (int cc = 0; cc < 64; cc += 4) {
            float4 v = (row < NN) ? *(const float4*)(ap + cc)
                                  : make_float4(0.f, 0.f, 0.f, 0.f);
            __nv_bfloat16 hx = __float2bfloat16_rn(v.x), hy = __float2bfloat16_rn(v.y);
            __nv_bfloat16 hz = __float2bfloat16_rn(v.z), hw = __float2bfloat16_rn(v.w);
            __nv_bfloat162 h0, h1, l0, l1;
            h0.x = hx; h0.y = hy; h1.x = hz; h1.y = hw;
            l0.x = __float2bfloat16_rn(v.x - __bfloat162float(hx));
            l0.y = __float2bfloat16_rn(v.y - __bfloat162float(hy));
            l1.x = __float2bfloat16_rn(v.z - __bfloat162float(hz));
            l1.y = __float2bfloat16_rn(v.w - __bfloat162float(hw));
            uint32_t so = swz(r, half * 64 + cc);
            *(__nv_bfloat162*)(sm + AHI + so)     = h0;
            *(__nv_bfloat162*)(sm + AHI + so + 4) = h1;
            *(__nv_bfloat162*)(sm + ALO + so)     = l0;
            *(__nv_bfloat162*)(sm + ALO + so + 4) = l1;
        }
    }
    __syncthreads();

    const int WARP_N = NC / 2;
    const int NPAIRS = WARP_N / 16;
    const int NB8    = WARP_N / 8;
    int warp_m = (wid & 3) * 32;
    int warp_n = (wid >> 2) * WARP_N;

    float c[2][NB8][4];
#pragma unroll
    for (int mb = 0; mb < 2; mb++)
#pragma unroll
        for (int nb = 0; nb < NB8; nb++)
#pragma unroll
            for (int j = 0; j < 4; j++) c[mb][nb][j] = 0.f;

    int a_r = ((lane >> 3) & 1) * 8 + (lane & 7);
    int a_c = (lane >> 4) * 8;
    int b_r = (lane >> 4) * 8 + (lane & 7);
    int b_c = ((lane >> 3) & 1) * 8;

#pragma unroll
    for (int pass = 0; pass < 3; pass++) {
        uint32_t abase = sb + (pass == 2 ? ALO : AHI);
        uint32_t bbase = sb + (pass == 1 ? BLO : BHI);
#pragma unroll
        for (int k = 0; k < 128; k += 16) {
            uint32_t afr[2][4];
#pragma unroll
            for (int mb = 0; mb < 2; mb++)
                ldsm_x4(afr[mb], abase + swz(warp_m + mb * 16 + a_r, k + a_c));
#pragma unroll
            for (int np = 0; np < NPAIRS; np++) {
                uint32_t bfr[4];
                ldsm_x4(bfr, bbase + swz(warp_n + np * 16 + b_r, k + b_c));
#pragma unroll
                for (int mb = 0; mb < 2; mb++) {
                    mma_bf16(c[mb][np * 2],     afr[mb], bfr);
                    mma_bf16(c[mb][np * 2 + 1], afr[mb], bfr + 2);
                }
            }
        }
    }

    int g = lane >> 2, tg = lane & 3;
    if (SPLIT) {
        bool is_u = (warp_n < 128);
#pragma unroll
        for (int mb = 0; mb < 2; mb++) {
#pragma unroll
            for (int nb = 0; nb < NB8; nb++) {
                int col = warp_n + nb * 8 + tg * 2;
                int r1 = row0 + warp_m + mb * 16 + g;
                int r2 = r1 + 8;
                if (is_u) {
                    if (r1 < NN)
                        *(__half2*)(UB + (size_t)r1 * 128 + col) =
                            __floats2half2_rn(c[mb][nb][0], c[mb][nb][1]);
                    if (r2 < NN)
                        *(__half2*)(UB + (size_t)r2 * 128 + col) =
                            __floats2half2_rn(c[mb][nb][2], c[mb][nb][3]);
                } else {
                    int cv = col - 128;
                    if (r1 < NN)
                        *(float2*)(V + (size_t)r1 * 128 + cv) =
                            make_float2(c[mb][nb][0], c[mb][nb][1]);
                    if (r2 < NN)
                        *(float2*)(V + (size_t)r2 * 128 + cv) =
                            make_float2(c[mb][nb][2], c[mb][nb][3]);
                }
            }
        }
    } else {
        const float* bs = (const float*)(sm + BIAS);
#pragma unroll
        for (int mb = 0; mb < 2; mb++) {
#pragma unroll
            for (int nb = 0; nb < NB8; nb++) {
                int col = warp_n + nb * 8 + tg * 2;
                float bx = bs[col], by = bs[col + 1];
                int r1 = row0 + warp_m + mb * 16 + g;
                if (r1 < NN)
                    *(float2*)(C + (size_t)r1 * NC + col) =
                        make_float2(c[mb][nb][0] + bx, c[mb][nb][1] + by);
                int r2 = r1 + 8;
                if (r2 < NN)
                    *(float2*)(C + (size_t)r2 * NC + col) =
                        make_float2(c[mb][nb][2] + bx, c[mb][nb][3] + by);
            }
        }
    }
}

// ---------------- aggregation: fp16 gather, fp32 accumulate ------------------
__global__ void __launch_bounds__(256) k_agg(
    const __half* __restrict__ ub,
    const float* __restrict__ v,
    const float* __restrict__ bias,
    const float* __restrict__ res,
    float* __restrict__ out) {
    int node = blockIdx.x * 8 + (threadIdx.x >> 5);
    if (node >= NN) return;
    int lane = threadIdx.x & 31;
    int off = g_off[node];
    int d = g_deg[node];

    float ax = 0.f, ay = 0.f, az = 0.f, aw = 0.f;
    const __half* uvb = ub + (size_t)lane * 4;

    int e = 0;
#pragma unroll 1
    for (; e + 4 <= d; e += 4) {
        int s0 = __ldg(&g_srcs[off + e]);
        int s1 = __ldg(&g_srcs[off + e + 1]);
        int s2 = __ldg(&g_srcs[off + e + 2]);
        int s3 = __ldg(&g_srcs[off + e + 3]);
        uint2 r0 = *(const uint2*)(uvb + (size_t)s0 * 128);
        uint2 r1 = *(const uint2*)(uvb + (size_t)s1 * 128);
        uint2 r2 = *(const uint2*)(uvb + (size_t)s2 * 128);
        uint2 r3 = *(const uint2*)(uvb + (size_t)s3 * 128);
        float2 a0 = __half22float2(*(__half2*)&r0.x), b0 = __half22float2(*(__half2*)&r0.y);
        float2 a1 = __half22float2(*(__half2*)&r1.x), b1 = __half22float2(*(__half2*)&r1.y);
        float2 a2 = __half22float2(*(__half2*)&r2.x), b2 = __half22float2(*(__half2*)&r2.y);
        float2 a3 = __half22float2(*(__half2*)&r3.x), b3 = __half22float2(*(__half2*)&r3.y);
        ax += a0.x + a1.x + a2.x + a3.x;
        ay += a0.y + a1.y + a2.y + a3.y;
        az += b0.x + b1.x + b2.x + b3.x;
        aw += b0.y + b1.y + b2.y + b3.y;
    }
    for (; e < d; e++) {
        int s = __ldg(&g_srcs[off + e]);
        uint2 r = *(const uint2*)(uvb + (size_t)s * 128);
        float2 a = __half22float2(*(__half2*)&r.x), b = __half22float2(*(__half2*)&r.y);
        ax += a.x; ay += a.y; az += b.x; aw += b.y;
    }

    float di = g_dinv[node];
    float4 vv = *(const float4*)(v + (size_t)node * 128 + lane * 4);
    float4 b = *(const float4*)(bias + lane * 4);
    float rx = fmaf(ax, di, vv.x + b.x);
    float ry = fmaf(ay, di, vv.y + b.y);
    float rz = fmaf(az, di, vv.z + b.z);
    float rw = fmaf(aw, di, vv.w + b.w);
    if (res) {
        float4 h = *(const float4*)(res + (size_t)node * 128 + lane * 4);
        rx += h.x; ry += h.y; rz += h.z; rw += h.w;
    }
    rx = fmaxf(rx, 0.f); ry = fmaxf(ry, 0.f);
    rz = fmaxf(rz, 0.f); rw = fmaxf(rw, 0.f);
    *(float4*)(out + (size_t)node * 128 + lane * 4) = make_float4(rx, ry, rz, rw);
}

// ---------------- launch ------------------------------------------------------
extern "C" void kernel_launch(void* const* d_in, const int* in_sizes, int n_in,
                              void* d_out, int out_size) {
    const float* x    = (const float*)d_in[0];
    const void*  ei   = d_in[1];
    const float* W1l  = (const float*)d_in[2];
    const float* b1   = (const float*)d_in[3];
    const float* W1r  = (const float*)d_in[4];
    const float* W2l  = (const float*)d_in[5];
    const float* b2   = (const float*)d_in[6];
    const float* W2r  = (const float*)d_in[7];
    const float* Wlin = (const float*)d_in[8];
    const float* blin = (const float*)d_in[9];
    float* out = (float*)d_out;

    const size_t SM_DUAL  = 1024 + 2 * 32768 + 2 * 256 * 256;
    const size_t SM_FINAL = 1024 + 2 * 32768 + 2 * 64 * 256;
    cudaFuncSetAttribute(k_gemm_mma<256, true>, cudaFuncAttributeMaxDynamicSharedMemorySize, (int)SM_DUAL);
    cudaFuncSetAttribute(k_gemm_mma<64, false>, cudaFuncAttributeMaxDynamicSharedMemorySize, (int)SM_FINAL);

    void *p_ub, *p_v, *p_h1, *p_h, *p_w1h, *p_w1l, *p_w2h, *p_w2l, *p_wfh, *p_wfl;
    cudaGetSymbolAddress(&p_ub, g_ub);
    cudaGetSymbolAddress(&p_v,  g_v);
    cudaGetSymbolAddress(&p_h1, g_h1);
    cudaGetSymbolAddress(&p_h,  g_h);
    cudaGetSymbolAddress(&p_w1h, g_w1hi);
    cudaGetSymbolAddress(&p_w1l, g_w1lo);
    cudaGetSymbolAddress(&p_w2h, g_w2hi);
    cudaGetSymbolAddress(&p_w2l, g_w2lo);
    cudaGetSymbolAddress(&p_wfh, g_wfhi);
    cudaGetSymbolAddress(&p_wfl, g_wflo);
    __half* ub = (__half*)p_ub;
    float*  vv = (float*)p_v;
    float*  h1 = (float*)p_h1;
    float*  h  = (float*)p_h;

    const int NB_N   = (NN + 255) / 256;
    const int NB_E   = (EE + 255) / 256;
    const int NB_SC  = (NN + 1023) / 1024;
    const int NB_TC  = (NN + 127) / 128;
    const int NB_AGG = (NN + 7) / 8;

    k_zero<<<NB_N, 256>>>();
    k_detect<<<16, 256>>>((const unsigned int*)ei);
    k_prep_w<<<(73728 + 255) / 256, 256>>>(W1l, W1r, W2l, W2r, Wlin);
    k_hist<<<NB_E, 256>>>(ei);
    k_scan1<<<NB_SC, 1024>>>();
    k_scan2<<<1, 128>>>();
    k_scan3<<<NB_SC, 1024>>>();
    k_scatter<<<NB_E, 256>>>(ei);

    k_gemm_mma<256, true><<<NB_TC, 256, SM_DUAL>>>(x, (unsigned char*)p_w1h, (unsigned char*)p_w1l, nullptr, nullptr, ub, vv);
    k_agg<<<NB_AGG, 256>>>(ub, vv, b1, nullptr, h1);
    k_gemm_mma<256, true><<<NB_TC, 256, SM_DUAL>>>(h1, (unsigned char*)p_w2h, (unsigned char*)p_w2l, nullptr, nullptr, ub, vv);
    k_agg<<<NB_AGG, 256>>>(ub, vv, b2, h1, h);
    k_gemm_mma<64, false><<<NB_TC, 256, SM_FINAL>>>(h, (unsigned char*)p_wfh, (unsigned char*)p_wfl, blin, out, nullptr, nullptr);
}